// round 16
// baseline (speedup 1.0000x reference)
#include <cuda_runtime.h>
#include <cuda_fp16.h>
#include <math.h>
#include <stdint.h>

#define BATCH 2
#define SEQ   2048
#define DM    1024
#define NH    16
#define DK    64

// fp16 scratch (device globals; no allocation allowed)
__device__ __half g_xh[BATCH * SEQ * DM];
__device__ __half g_Wqh[DM * DM];
__device__ __half g_Wkh[DM * DM];
__device__ __half g_Wvh[DM * DM];
__device__ __half g_Woh[DM * DM];
__device__ __half g_Qh[BATCH * NH * SEQ * DK];   // roped, x0.125
__device__ __half g_Kh[BATCH * NH * SEQ * DK];   // roped
__device__ __half g_Vh[BATCH * NH * SEQ * DK];
__device__ __half g_Oh[BATCH * SEQ * DM];

__device__ __forceinline__ uint32_t h2u(__half2 h) {
    return *reinterpret_cast<uint32_t*>(&h);
}
__device__ __forceinline__ uint32_t f2h2u(float a, float b) {
    __half2 h = __floats2half2_rn(a, b);
    return *reinterpret_cast<uint32_t*>(&h);
}

__device__ __forceinline__ void mma_f16(
    float& d0, float& d1, float& d2, float& d3,
    uint32_t a0, uint32_t a1, uint32_t a2, uint32_t a3,
    uint32_t b0, uint32_t b1)
{
    asm volatile(
        "mma.sync.aligned.m16n8k16.row.col.f32.f16.f16.f32 "
        "{%0,%1,%2,%3}, {%4,%5,%6,%7}, {%8,%9}, {%0,%1,%2,%3};\n"
        : "+f"(d0), "+f"(d1), "+f"(d2), "+f"(d3)
        : "r"(a0), "r"(a1), "r"(a2), "r"(a3), "r"(b0), "r"(b1));
}

__device__ __forceinline__ void ldsm_x4(
    uint32_t& r0, uint32_t& r1, uint32_t& r2, uint32_t& r3, uint32_t addr)
{
    asm volatile("ldmatrix.sync.aligned.m8n8.x4.shared.b16 {%0,%1,%2,%3}, [%4];"
                 : "=r"(r0), "=r"(r1), "=r"(r2), "=r"(r3) : "r"(addr));
}
__device__ __forceinline__ void ldsm_x4_t(
    uint32_t& r0, uint32_t& r1, uint32_t& r2, uint32_t& r3, uint32_t addr)
{
    asm volatile("ldmatrix.sync.aligned.m8n8.x4.trans.shared.b16 {%0,%1,%2,%3}, [%4];"
                 : "=r"(r0), "=r"(r1), "=r"(r2), "=r"(r3) : "r"(addr));
}

__device__ __forceinline__ void cp16(uint32_t saddr, const void* gptr) {
    asm volatile("cp.async.cg.shared.global [%0], [%1], 16;\n"
                 :: "r"(saddr), "l"(gptr));
}
#define CP_COMMIT() asm volatile("cp.async.commit_group;\n" ::: "memory")
#define CP_WAIT2()  asm volatile("cp.async.wait_group 2;\n" ::: "memory")
#define CP_WAIT1()  asm volatile("cp.async.wait_group 1;\n" ::: "memory")
#define CP_WAIT0()  asm volatile("cp.async.wait_group 0;\n" ::: "memory")

// ================= fp32 -> fp16 pre-convert =================================
#define NX (BATCH * SEQ * DM)
#define NW (DM * DM)

__global__ __launch_bounds__(256) void cvt_kernel(
    const float* __restrict__ x,
    const float* __restrict__ wq,
    const float* __restrict__ wk,
    const float* __restrict__ wv,
    const float* __restrict__ wo)
{
    const size_t base = ((size_t)blockIdx.x * 256 + threadIdx.x) * 8;
    const float* src;
    __half* dst;
    size_t off;
    if (base < NX)               { src = x;  dst = g_xh;  off = base; }
    else if (base < NX + NW)     { src = wq; dst = g_Wqh; off = base - NX; }
    else if (base < NX + 2 * NW) { src = wk; dst = g_Wkh; off = base - NX - NW; }
    else if (base < NX + 3 * NW) { src = wv; dst = g_Wvh; off = base - NX - 2 * NW; }
    else                         { src = wo; dst = g_Woh; off = base - NX - 3 * NW; }

    float4 f0 = *(const float4*)(src + off);
    float4 f1 = *(const float4*)(src + off + 4);
    uint4 o;
    o.x = f2h2u(f0.x, f0.y); o.y = f2h2u(f0.z, f0.w);
    o.z = f2h2u(f1.x, f1.y); o.w = f2h2u(f1.z, f1.w);
    *(uint4*)(dst + off) = o;
}

// ============== fp16 GEMM: 128x128x32, cp.async 3-stage + ldmatrix ==========
#define TBM 128
#define TBN 128
#define TBK 32
#define ASTRIDE 40
#define BSTRIDE 136
#define A_BYTES (128 * ASTRIDE * 2)
#define B_BYTES (32 * BSTRIDE * 2)
#define STAGE_BYTES (A_BYTES + B_BYTES)  // 18944
#define GEMM_SMEM (3 * STAGE_BYTES)      // 56832

#define GEMM_BODY(A_, W_)                                                      \
    extern __shared__ __half smg[];                                            \
    const uint32_t sbase = (uint32_t)__cvta_generic_to_shared(smg);            \
    const int m0 = blockIdx.y * TBM;                                           \
    const int n0 = blockIdx.x * TBN;                                           \
    const int tid  = threadIdx.x;                                              \
    const int lane = tid & 31;                                                 \
    const int wid  = tid >> 5;                                                 \
    const int wm = wid >> 2;                                                   \
    const int wn = wid & 3;                                                    \
    const int lr = lane >> 2;                                                  \
    const int lc = lane & 3;                                                   \
    const int q8 = lane >> 3, r8 = lane & 7;                                   \
    uint32_t aoff[4], boff[2];                                                 \
    _Pragma("unroll")                                                          \
    for (int mf = 0; mf < 4; mf++)                                             \
        aoff[mf] = ((wm * 64 + mf * 16 + (q8 & 1) * 8 + r8) * ASTRIDE          \
                    + (q8 >> 1) * 8) * 2;                                      \
    _Pragma("unroll")                                                          \
    for (int pr = 0; pr < 2; pr++)                                             \
        boff[pr] = (((q8 & 1) * 8 + r8) * BSTRIDE                              \
                    + wn * 32 + pr * 16 + (q8 >> 1) * 8) * 2;                  \
    const int ar = tid >> 2, ac = tid & 3;                                     \
    const int br = tid >> 4, bc = tid & 15;                                    \
    float acc[4][4][4];                                                        \
    _Pragma("unroll")                                                          \
    for (int i = 0; i < 4; i++)                                                \
        _Pragma("unroll")                                                      \
        for (int j = 0; j < 4; j++)                                            \
            _Pragma("unroll")                                                  \
            for (int r = 0; r < 4; r++) acc[i][j][r] = 0.f;                    \
    auto issue = [&](int kt, int s) {                                          \
        const uint32_t ab = sbase + s * STAGE_BYTES;                           \
        const uint32_t bb = ab + A_BYTES;                                      \
        const int k0 = kt * TBK;                                               \
        cp16(ab + (ar * ASTRIDE + ac * 8) * 2,                                 \
             A_ + (size_t)(m0 + ar) * DM + k0 + ac * 8);                       \
        cp16(ab + ((ar + 64) * ASTRIDE + ac * 8) * 2,                          \
             A_ + (size_t)(m0 + ar + 64) * DM + k0 + ac * 8);                  \
        cp16(bb + (br * BSTRIDE + bc * 8) * 2,                                 \
             W_ + (size_t)(k0 + br) * DM + n0 + bc * 8);                       \
        cp16(bb + ((br + 16) * BSTRIDE + bc * 8) * 2,                          \
             W_ + (size_t)(k0 + br + 16) * DM + n0 + bc * 8);                  \
        CP_COMMIT();                                                           \
    };                                                                         \
    issue(0, 0);                                                               \
    issue(1, 1);                                                               \
    const int NT = DM / TBK;   /* 32 */                                        \
    for (int kt = 0; kt < NT; kt++) {                                          \
        const int s = kt % 3;                                                  \
        if (kt + 1 < NT) { CP_WAIT1(); } else { CP_WAIT0(); }                  \
        __syncthreads();                                                       \
        if (kt + 2 < NT) issue(kt + 2, (kt + 2) % 3);                          \
        const uint32_t ab = sbase + s * STAGE_BYTES;                           \
        const uint32_t bb = ab + A_BYTES;                                      \
        _Pragma("unroll")                                                      \
        for (int ks = 0; ks < 2; ks++) {                                       \
            uint32_t af[4][4], bf[4][2];                                       \
            _Pragma("unroll")                                                  \
            for (int mf = 0; mf < 4; mf++)                                     \
                ldsm_x4(af[mf][0], af[mf][1], af[mf][2], af[mf][3],            \
                        ab + aoff[mf] + ks * 32);                              \
            ldsm_x4_t(bf[0][0], bf[0][1], bf[1][0], bf[1][1],                  \
                      bb + boff[0] + ks * (16 * BSTRIDE * 2));                 \
            ldsm_x4_t(bf[2][0], bf[2][1], bf[3][0], bf[3][1],                  \
                      bb + boff[1] + ks * (16 * BSTRIDE * 2));                 \
            _Pragma("unroll")                                                  \
            for (int mf = 0; mf < 4; mf++)                                     \
                _Pragma("unroll")                                              \
                for (int nf = 0; nf < 4; nf++)                                 \
                    mma_f16(acc[mf][nf][0], acc[mf][nf][1],                    \
                            acc[mf][nf][2], acc[mf][nf][3],                    \
                            af[mf][0], af[mf][1], af[mf][2], af[mf][3],        \
                            bf[nf][0], bf[nf][1]);                             \
        }                                                                      \
    }

// ============ QKV GEMM: fused RoPE epilogue =================================
__global__ __launch_bounds__(256) void gemm_qkv_kernel(const int* __restrict__ pos)
{
    const int z = blockIdx.z;
    const __half* __restrict__ W =
        (z == 0) ? g_Wqh : (z == 1) ? g_Wkh : g_Wvh;
    __half* __restrict__ dsth = (z == 0) ? g_Qh : (z == 1) ? g_Kh : g_Vh;
    const __half* __restrict__ A = g_xh;

    GEMM_BODY(A, W)

    const int rb = m0 + wm * 64 + lr;
    const int cb = n0 + wn * 32 + 2 * lc;

    float invf[4];
    #pragma unroll
    for (int nf = 0; nf < 4; nf++) {
        const int d = (cb + nf * 8) & 63;
        invf[nf] = 1.0f / powf(10000.0f, (float)d / 64.0f);
    }
    const float qscale = (z == 0) ? 0.125f : 1.0f;

    #pragma unroll
    for (int mf = 0; mf < 4; mf++) {
        #pragma unroll
        for (int half = 0; half < 2; half++) {
            const int m = rb + mf * 16 + half * 8;
            const int b_ = m >> 11, s_ = m & (SEQ - 1);
            const float p = (float)pos[b_ * SEQ + s_];
            #pragma unroll
            for (int nf = 0; nf < 4; nf++) {
                const int n = cb + nf * 8;
                const int h = n >> 6, d = n & 63;
                const float ve = acc[mf][nf][half * 2];
                const float vo = acc[mf][nf][half * 2 + 1];
                float re, ro;
                if (z < 2) {
                    float sn, cs;
                    sincosf(p * invf[nf], &sn, &cs);
                    re = (ve * cs - vo * sn) * qscale;
                    ro = (ve * sn + vo * cs) * qscale;
                } else {
                    re = ve; ro = vo;
                }
                __half2* dp = (__half2*)(dsth + (((size_t)(b_ * NH + h)) * SEQ + s_) * DK + d);
                *dp = __floats2half2_rn(re, ro);
            }
        }
    }
}

// ============ WO GEMM ========================================================
__global__ __launch_bounds__(256) void gemm_out_kernel(float* __restrict__ out)
{
    const __half* __restrict__ A = g_Oh;
    const __half* __restrict__ W = g_Woh;

    GEMM_BODY(A, W)

    const int rb = m0 + wm * 64 + lr;
    const int cb = n0 + wn * 32 + 2 * lc;
    #pragma unroll
    for (int mf = 0; mf < 4; mf++) {
        #pragma unroll
        for (int nf = 0; nf < 4; nf++) {
            const int n = cb + nf * 8;
            #pragma unroll
            for (int half = 0; half < 2; half++) {
                const int m = rb + mf * 16 + half * 8;
                *(float2*)(out + (size_t)m * DM + n) =
                    make_float2(acc[mf][nf][half * 2], acc[mf][nf][half * 2 + 1]);
            }
        }
    }
}

// ====== fp16 flash attention: FBM=128 (8 warps), cp.async 3-stage K/V =======
#define FBM 128
#define FBN 64
#define FSTR 72
#define FQ_BYTES (FBM * FSTR * 2)          // 18432
#define FK_BYTES (FBN * FSTR * 2)          // 9216
#define FSTAGE_BYTES (2 * FK_BYTES)        // 18432
#define FLASH_SMEM (FQ_BYTES + 3 * FSTAGE_BYTES)   // 73728

__global__ __launch_bounds__(256, 2) void flash_f16_kernel()
{
    extern __shared__ __half fsh[];
    const uint32_t fbase = (uint32_t)__cvta_generic_to_shared(fsh);
    const uint32_t qb = fbase;

    const int bh = blockIdx.y;
    const int m0 = ((int)gridDim.x - 1 - (int)blockIdx.x) * FBM;   // heavy first
    const int tid  = threadIdx.x;
    const int lane = tid & 31;
    const int w    = tid >> 5;          // 0..7, owns rows w*16..w*16+15
    const int lr   = lane >> 2;
    const int lc   = lane & 3;
    const int q8 = lane >> 3, r8 = lane & 7;

    const __half* __restrict__ Qb = g_Qh + (size_t)bh * SEQ * DK;
    const __half* __restrict__ Kb = g_Kh + (size_t)bh * SEQ * DK;
    const __half* __restrict__ Vb = g_Vh + (size_t)bh * SEQ * DK;

    const uint32_t qoff =
        ((w * 16 + (q8 & 1) * 8 + r8) * FSTR + (q8 >> 1) * 8) * 2;
    const uint32_t koff =
        ((((lane >> 4) & 1) * 8 + (lane & 7)) * FSTR + ((lane >> 3) & 1) * 8) * 2;
    const uint32_t voff =
        (((q8 & 1) * 8 + r8) * FSTR + (q8 >> 1) * 8) * 2;

    // ---- stage Q via cp.async: 128 rows x 8 chunks = 1024, 4 per thread ----
    {
        #pragma unroll
        for (int it = 0; it < 4; it++) {
            const int idx = tid + it * 256;
            const int row = idx >> 3, ch = idx & 7;
            cp16(qb + (row * FSTR + ch * 8) * 2,
                 Qb + (size_t)(m0 + row) * DK + ch * 8);
        }
        CP_COMMIT();
    }

    auto issue_kv = [&](int t, int s) {
        const uint32_t kb = fbase + FQ_BYTES + s * FSTAGE_BYTES;
        const uint32_t vb = kb + FK_BYTES;
        const int j0 = t * FBN;
        #pragma unroll
        for (int it = 0; it < 2; it++) {
            const int idx = tid + it * 256;        // 0..511
            const int row = idx >> 3, ch = idx & 7;
            cp16(kb + (row * FSTR + ch * 8) * 2,
                 Kb + (size_t)(j0 + row) * DK + ch * 8);
            cp16(vb + (row * FSTR + ch * 8) * 2,
                 Vb + (size_t)(j0 + row) * DK + ch * 8);
        }
        CP_COMMIT();
    };

    const int nt = m0 / FBN + 2;        // KV tiles cover cols 0 .. m0+127
    issue_kv(0, 0);
    issue_kv(1, 1);                     // nt >= 2 always

    uint32_t qf[4][4];
    {
        CP_WAIT2();                     // Q group done (2 KV groups pending)
        __syncthreads();
        #pragma unroll
        for (int ks = 0; ks < 4; ks++)
            ldsm_x4(qf[ks][0], qf[ks][1], qf[ks][2], qf[ks][3],
                    qb + qoff + ks * 32);
    }

    float o[8][4];
    #pragma unroll
    for (int n = 0; n < 8; n++)
        #pragma unroll
        for (int c = 0; c < 4; c++) o[n][c] = 0.f;
    float mrow0 = -1e30f, mrow1 = -1e30f, lrow0 = 0.f, lrow1 = 0.f;

    const int gr_lo = m0 + w * 16;      // first global row this warp owns

    for (int t = 0; t < nt; t++) {
        const int s = t % 3;
        if (t + 1 < nt) { CP_WAIT1(); } else { CP_WAIT0(); }
        __syncthreads();
        if (t + 2 < nt) issue_kv(t + 2, (t + 2) % 3);

        const int j0 = t * FBN;
        // warps fully above the diagonal skip compute on this tile
        if (j0 > gr_lo + 15) { __syncthreads(); continue; }

        const uint32_t kb = fbase + FQ_BYTES + s * FSTAGE_BYTES;
        const uint32_t vb = kb + FK_BYTES;

        // ---- S = Q K^T ----
        float sacc[8][4];
        #pragma unroll
        for (int n = 0; n < 8; n++)
            #pragma unroll
            for (int c = 0; c < 4; c++) sacc[n][c] = 0.f;

        #pragma unroll
        for (int ks = 0; ks < 4; ks++) {
            #pragma unroll
            for (int jp = 0; jp < 4; jp++) {
                uint32_t b0a, b1a, b0b, b1b;
                ldsm_x4(b0a, b1a, b0b, b1b,
                        kb + koff + (jp * 16 * FSTR + ks * 16) * 2);
                mma_f16(sacc[2*jp][0], sacc[2*jp][1], sacc[2*jp][2], sacc[2*jp][3],
                        qf[ks][0], qf[ks][1], qf[ks][2], qf[ks][3], b0a, b1a);
                mma_f16(sacc[2*jp+1][0], sacc[2*jp+1][1], sacc[2*jp+1][2], sacc[2*jp+1][3],
                        qf[ks][0], qf[ks][1], qf[ks][2], qf[ks][3], b0b, b1b);
            }
        }

        // ---- causal mask on diagonal-crossing tiles ----
        if (j0 + FBN - 1 > gr_lo) {
            const int r0 = gr_lo + lr;
            #pragma unroll
            for (int n = 0; n < 8; n++) {
                const int c0 = j0 + n * 8 + 2 * lc;
                if (c0     > r0)     sacc[n][0] = -1e30f;
                if (c0 + 1 > r0)     sacc[n][1] = -1e30f;
                if (c0     > r0 + 8) sacc[n][2] = -1e30f;
                if (c0 + 1 > r0 + 8) sacc[n][3] = -1e30f;
            }
        }

        // ---- online softmax ----
        float mx0 = -1e30f, mx1 = -1e30f;
        #pragma unroll
        for (int n = 0; n < 8; n++) {
            mx0 = fmaxf(mx0, fmaxf(sacc[n][0], sacc[n][1]));
            mx1 = fmaxf(mx1, fmaxf(sacc[n][2], sacc[n][3]));
        }
        mx0 = fmaxf(mx0, __shfl_xor_sync(0xffffffffu, mx0, 1));
        mx0 = fmaxf(mx0, __shfl_xor_sync(0xffffffffu, mx0, 2));
        mx1 = fmaxf(mx1, __shfl_xor_sync(0xffffffffu, mx1, 1));
        mx1 = fmaxf(mx1, __shfl_xor_sync(0xffffffffu, mx1, 2));

        const float mn0 = fmaxf(mrow0, mx0);
        const float mn1 = fmaxf(mrow1, mx1);
        const float sc0 = __expf(mrow0 - mn0);
        const float sc1 = __expf(mrow1 - mn1);
        lrow0 *= sc0; lrow1 *= sc1;
        #pragma unroll
        for (int n = 0; n < 8; n++) {
            o[n][0] *= sc0; o[n][1] *= sc0;
            o[n][2] *= sc1; o[n][3] *= sc1;
        }
        mrow0 = mn0; mrow1 = mn1;

        uint32_t pv[8][2];
        #pragma unroll
        for (int n = 0; n < 8; n++) {
            const float p0 = __expf(sacc[n][0] - mn0);
            const float p1 = __expf(sacc[n][1] - mn0);
            const float p2 = __expf(sacc[n][2] - mn1);
            const float p3 = __expf(sacc[n][3] - mn1);
            lrow0 += p0 + p1;
            lrow1 += p2 + p3;
            pv[n][0] = f2h2u(p0, p1);
            pv[n][1] = f2h2u(p2, p3);
        }

        // ---- O += P V ----
        #pragma unroll
        for (int ks = 0; ks < 4; ks++) {
            const uint32_t a0 = pv[2 * ks    ][0];
            const uint32_t a1 = pv[2 * ks    ][1];
            const uint32_t a2 = pv[2 * ks + 1][0];
            const uint32_t a3 = pv[2 * ks + 1][1];
            #pragma unroll
            for (int np = 0; np < 2; np++) {
                uint32_t b0a, b1a, b0b, b1b;
                ldsm_x4_t(b0a, b1a, b0b, b1b,
                          vb + voff + (ks * 16 * FSTR + np * 32) * 2);
                mma_f16(o[4*np  ][0], o[4*np  ][1], o[4*np  ][2], o[4*np  ][3],
                        a0, a1, a2, a3, b0a, b1a);
                mma_f16(o[4*np+1][0], o[4*np+1][1], o[4*np+1][2], o[4*np+1][3],
                        a0, a1, a2, a3, b0b, b1b);
                uint32_t c0a, c1a, c0b, c1b;
                ldsm_x4_t(c0a, c1a, c0b, c1b,
                          vb + voff + (ks * 16 * FSTR + np * 32 + 16) * 2);
                mma_f16(o[4*np+2][0], o[4*np+2][1], o[4*np+2][2], o[4*np+2][3],
                        a0, a1, a2, a3, c0a, c1a);
                mma_f16(o[4*np+3][0], o[4*np+3][1], o[4*np+3][2], o[4*np+3][3],
                        a0, a1, a2, a3, c0b, c1b);
            }
        }
        __syncthreads();   // all warps done with stage s before overwrite
    }

    lrow0 += __shfl_xor_sync(0xffffffffu, lrow0, 1);
    lrow0 += __shfl_xor_sync(0xffffffffu, lrow0, 2);
    lrow1 += __shfl_xor_sync(0xffffffffu, lrow1, 1);
    lrow1 += __shfl_xor_sync(0xffffffffu, lrow1, 2);
    const float inv0 = 1.0f / lrow0;
    const float inv1 = 1.0f / lrow1;

    const int b_ = bh >> 4, h = bh & 15;
    const int r0 = m0 + w * 16 + lr;
    const int r1 = r0 + 8;
    #pragma unroll
    for (int n = 0; n < 8; n++) {
        const int d = h * 64 + n * 8 + 2 * lc;
        *(__half2*)(g_Oh + ((size_t)b_ * SEQ + r0) * DM + d) =
            __floats2half2_rn(o[n][0] * inv0, o[n][1] * inv0);
        *(__half2*)(g_Oh + ((size_t)b_ * SEQ + r1) * DM + d) =
            __floats2half2_rn(o[n][2] * inv1, o[n][3] * inv1);
    }
}

// ---------------- launch ----------------------------------------------------
extern "C" void kernel_launch(void* const* d_in, const int* in_sizes, int n_in,
                              void* d_out, int out_size)
{
    (void)in_sizes; (void)n_in; (void)out_size;
    const float* x   = (const float*)d_in[0];
    const int*   pos = (const int*)  d_in[1];
    const float* WQ  = (const float*)d_in[2];
    const float* WK  = (const float*)d_in[3];
    const float* WV  = (const float*)d_in[4];
    const float* WO  = (const float*)d_in[5];
    float* out = (float*)d_out;

    cudaFuncSetAttribute(gemm_qkv_kernel,
                         cudaFuncAttributeMaxDynamicSharedMemorySize, GEMM_SMEM);
    cudaFuncSetAttribute(gemm_out_kernel,
                         cudaFuncAttributeMaxDynamicSharedMemorySize, GEMM_SMEM);
    cudaFuncSetAttribute(flash_f16_kernel,
                         cudaFuncAttributeMaxDynamicSharedMemorySize, FLASH_SMEM);

    const int ncvt = (NX + 4 * NW) / (8 * 256);
    cvt_kernel<<<ncvt, 256>>>(x, WQ, WK, WV, WO);

    dim3 gq(DM / TBN, (BATCH * SEQ) / TBM, 3);      // (8, 32, 3)
    gemm_qkv_kernel<<<gq, 256, GEMM_SMEM>>>(pos);

    dim3 gf(SEQ / FBM, BATCH * NH);                 // (16, 32)
    flash_f16_kernel<<<gf, 256, FLASH_SMEM>>>();

    dim3 go(DM / TBN, (BATCH * SEQ) / TBM, 1);      // (8, 32)
    gemm_out_kernel<<<go, 256, GEMM_SMEM>>>(out);
}

// round 17
// speedup vs baseline: 1.0431x; 1.0431x over previous
#include <cuda_runtime.h>
#include <cuda_fp16.h>
#include <math.h>
#include <stdint.h>

#define BATCH 2
#define SEQ   2048
#define DM    1024
#define NH    16
#define DK    64

// fp16 scratch (device globals; no allocation allowed)
__device__ __half g_xh[BATCH * SEQ * DM];
__device__ __half g_Wqh[DM * DM];
__device__ __half g_Wkh[DM * DM];
__device__ __half g_Wvh[DM * DM];
__device__ __half g_Woh[DM * DM];
__device__ __half g_Qh[BATCH * NH * SEQ * DK];   // roped, x0.125
__device__ __half g_Kh[BATCH * NH * SEQ * DK];   // roped
__device__ __half g_Vh[BATCH * NH * SEQ * DK];
__device__ __half g_Oh[BATCH * SEQ * DM];

__device__ __forceinline__ uint32_t h2u(__half2 h) {
    return *reinterpret_cast<uint32_t*>(&h);
}
__device__ __forceinline__ uint32_t f2h2u(float a, float b) {
    __half2 h = __floats2half2_rn(a, b);
    return *reinterpret_cast<uint32_t*>(&h);
}

__device__ __forceinline__ void mma_f16(
    float& d0, float& d1, float& d2, float& d3,
    uint32_t a0, uint32_t a1, uint32_t a2, uint32_t a3,
    uint32_t b0, uint32_t b1)
{
    asm volatile(
        "mma.sync.aligned.m16n8k16.row.col.f32.f16.f16.f32 "
        "{%0,%1,%2,%3}, {%4,%5,%6,%7}, {%8,%9}, {%0,%1,%2,%3};\n"
        : "+f"(d0), "+f"(d1), "+f"(d2), "+f"(d3)
        : "r"(a0), "r"(a1), "r"(a2), "r"(a3), "r"(b0), "r"(b1));
}

__device__ __forceinline__ void ldsm_x4(
    uint32_t& r0, uint32_t& r1, uint32_t& r2, uint32_t& r3, uint32_t addr)
{
    asm volatile("ldmatrix.sync.aligned.m8n8.x4.shared.b16 {%0,%1,%2,%3}, [%4];"
                 : "=r"(r0), "=r"(r1), "=r"(r2), "=r"(r3) : "r"(addr));
}
__device__ __forceinline__ void ldsm_x4_t(
    uint32_t& r0, uint32_t& r1, uint32_t& r2, uint32_t& r3, uint32_t addr)
{
    asm volatile("ldmatrix.sync.aligned.m8n8.x4.trans.shared.b16 {%0,%1,%2,%3}, [%4];"
                 : "=r"(r0), "=r"(r1), "=r"(r2), "=r"(r3) : "r"(addr));
}

__device__ __forceinline__ void cp16(uint32_t saddr, const void* gptr) {
    asm volatile("cp.async.cg.shared.global [%0], [%1], 16;\n"
                 :: "r"(saddr), "l"(gptr));
}
#define CP_COMMIT() asm volatile("cp.async.commit_group;\n" ::: "memory")
#define CP_WAIT2()  asm volatile("cp.async.wait_group 2;\n" ::: "memory")
#define CP_WAIT1()  asm volatile("cp.async.wait_group 1;\n" ::: "memory")
#define CP_WAIT0()  asm volatile("cp.async.wait_group 0;\n" ::: "memory")

// ================= fp32 -> fp16 pre-convert =================================
#define NX (BATCH * SEQ * DM)
#define NW (DM * DM)

__global__ __launch_bounds__(256) void cvt_kernel(
    const float* __restrict__ x,
    const float* __restrict__ wq,
    const float* __restrict__ wk,
    const float* __restrict__ wv,
    const float* __restrict__ wo)
{
    const size_t base = ((size_t)blockIdx.x * 256 + threadIdx.x) * 8;
    const float* src;
    __half* dst;
    size_t off;
    if (base < NX)               { src = x;  dst = g_xh;  off = base; }
    else if (base < NX + NW)     { src = wq; dst = g_Wqh; off = base - NX; }
    else if (base < NX + 2 * NW) { src = wk; dst = g_Wkh; off = base - NX - NW; }
    else if (base < NX + 3 * NW) { src = wv; dst = g_Wvh; off = base - NX - 2 * NW; }
    else                         { src = wo; dst = g_Woh; off = base - NX - 3 * NW; }

    float4 f0 = *(const float4*)(src + off);
    float4 f1 = *(const float4*)(src + off + 4);
    uint4 o;
    o.x = f2h2u(f0.x, f0.y); o.y = f2h2u(f0.z, f0.w);
    o.z = f2h2u(f1.x, f1.y); o.w = f2h2u(f1.z, f1.w);
    *(uint4*)(dst + off) = o;
}

// ============== fp16 GEMM: 128x128x32, cp.async 4-stage + ldmatrix ==========
#define TBM 128
#define TBN 128
#define TBK 32
#define ASTRIDE 40
#define BSTRIDE 136
#define A_BYTES (128 * ASTRIDE * 2)
#define B_BYTES (32 * BSTRIDE * 2)
#define STAGE_BYTES (A_BYTES + B_BYTES)  // 18944
#define NSTAGE 4
#define GEMM_SMEM (NSTAGE * STAGE_BYTES) // 75776

#define GEMM_BODY(A_, W_)                                                      \
    extern __shared__ __half smg[];                                            \
    const uint32_t sbase = (uint32_t)__cvta_generic_to_shared(smg);            \
    const int m0 = blockIdx.y * TBM;                                           \
    const int n0 = blockIdx.x * TBN;                                           \
    const int tid  = threadIdx.x;                                              \
    const int lane = tid & 31;                                                 \
    const int wid  = tid >> 5;                                                 \
    const int wm = wid >> 2;                                                   \
    const int wn = wid & 3;                                                    \
    const int lr = lane >> 2;                                                  \
    const int lc = lane & 3;                                                   \
    const int q8 = lane >> 3, r8 = lane & 7;                                   \
    uint32_t aoff[4], boff[2];                                                 \
    _Pragma("unroll")                                                          \
    for (int mf = 0; mf < 4; mf++)                                             \
        aoff[mf] = ((wm * 64 + mf * 16 + (q8 & 1) * 8 + r8) * ASTRIDE          \
                    + (q8 >> 1) * 8) * 2;                                      \
    _Pragma("unroll")                                                          \
    for (int pr = 0; pr < 2; pr++)                                             \
        boff[pr] = (((q8 & 1) * 8 + r8) * BSTRIDE                              \
                    + wn * 32 + pr * 16 + (q8 >> 1) * 8) * 2;                  \
    const int ar = tid >> 2, ac = tid & 3;                                     \
    const int br = tid >> 4, bc = tid & 15;                                    \
    float acc[4][4][4];                                                        \
    _Pragma("unroll")                                                          \
    for (int i = 0; i < 4; i++)                                                \
        _Pragma("unroll")                                                      \
        for (int j = 0; j < 4; j++)                                            \
            _Pragma("unroll")                                                  \
            for (int r = 0; r < 4; r++) acc[i][j][r] = 0.f;                    \
    auto issue = [&](int kt, int s) {                                          \
        const uint32_t ab = sbase + s * STAGE_BYTES;                           \
        const uint32_t bb = ab + A_BYTES;                                      \
        const int k0 = kt * TBK;                                               \
        cp16(ab + (ar * ASTRIDE + ac * 8) * 2,                                 \
             A_ + (size_t)(m0 + ar) * DM + k0 + ac * 8);                       \
        cp16(ab + ((ar + 64) * ASTRIDE + ac * 8) * 2,                          \
             A_ + (size_t)(m0 + ar + 64) * DM + k0 + ac * 8);                  \
        cp16(bb + (br * BSTRIDE + bc * 8) * 2,                                 \
             W_ + (size_t)(k0 + br) * DM + n0 + bc * 8);                       \
        cp16(bb + ((br + 16) * BSTRIDE + bc * 8) * 2,                          \
             W_ + (size_t)(k0 + br + 16) * DM + n0 + bc * 8);                  \
        CP_COMMIT();                                                           \
    };                                                                         \
    issue(0, 0);                                                               \
    issue(1, 1);                                                               \
    issue(2, 2);                                                               \
    const int NT = DM / TBK;   /* 32 */                                        \
    for (int kt = 0; kt < NT; kt++) {                                          \
        const int s = kt & 3;                                                  \
        if (kt + 2 < NT)      { CP_WAIT2(); }                                  \
        else if (kt + 1 < NT) { CP_WAIT1(); }                                  \
        else                  { CP_WAIT0(); }                                  \
        __syncthreads();                                                       \
        if (kt + 3 < NT) issue(kt + 3, (kt + 3) & 3);                          \
        const uint32_t ab = sbase + s * STAGE_BYTES;                           \
        const uint32_t bb = ab + A_BYTES;                                      \
        _Pragma("unroll")                                                      \
        for (int ks = 0; ks < 2; ks++) {                                       \
            uint32_t af[4][4], bf[4][2];                                       \
            _Pragma("unroll")                                                  \
            for (int mf = 0; mf < 4; mf++)                                     \
                ldsm_x4(af[mf][0], af[mf][1], af[mf][2], af[mf][3],            \
                        ab + aoff[mf] + ks * 32);                              \
            ldsm_x4_t(bf[0][0], bf[0][1], bf[1][0], bf[1][1],                  \
                      bb + boff[0] + ks * (16 * BSTRIDE * 2));                 \
            ldsm_x4_t(bf[2][0], bf[2][1], bf[3][0], bf[3][1],                  \
                      bb + boff[1] + ks * (16 * BSTRIDE * 2));                 \
            _Pragma("unroll")                                                  \
            for (int mf = 0; mf < 4; mf++)                                     \
                _Pragma("unroll")                                              \
                for (int nf = 0; nf < 4; nf++)                                 \
                    mma_f16(acc[mf][nf][0], acc[mf][nf][1],                    \
                            acc[mf][nf][2], acc[mf][nf][3],                    \
                            af[mf][0], af[mf][1], af[mf][2], af[mf][3],        \
                            bf[nf][0], bf[nf][1]);                             \
        }                                                                      \
    }

// ============ QKV GEMM: fused RoPE epilogue =================================
__global__ __launch_bounds__(256) void gemm_qkv_kernel(const int* __restrict__ pos)
{
    const int z = blockIdx.z;
    const __half* __restrict__ W =
        (z == 0) ? g_Wqh : (z == 1) ? g_Wkh : g_Wvh;
    __half* __restrict__ dsth = (z == 0) ? g_Qh : (z == 1) ? g_Kh : g_Vh;
    const __half* __restrict__ A = g_xh;

    GEMM_BODY(A, W)

    const int rb = m0 + wm * 64 + lr;
    const int cb = n0 + wn * 32 + 2 * lc;

    float invf[4];
    #pragma unroll
    for (int nf = 0; nf < 4; nf++) {
        const int d = (cb + nf * 8) & 63;
        invf[nf] = 1.0f / powf(10000.0f, (float)d / 64.0f);
    }
    const float qscale = (z == 0) ? 0.125f : 1.0f;

    #pragma unroll
    for (int mf = 0; mf < 4; mf++) {
        #pragma unroll
        for (int half = 0; half < 2; half++) {
            const int m = rb + mf * 16 + half * 8;
            const int b_ = m >> 11, s_ = m & (SEQ - 1);
            const float p = (float)pos[b_ * SEQ + s_];
            #pragma unroll
            for (int nf = 0; nf < 4; nf++) {
                const int n = cb + nf * 8;
                const int h = n >> 6, d = n & 63;
                const float ve = acc[mf][nf][half * 2];
                const float vo = acc[mf][nf][half * 2 + 1];
                float re, ro;
                if (z < 2) {
                    float sn, cs;
                    sincosf(p * invf[nf], &sn, &cs);
                    re = (ve * cs - vo * sn) * qscale;
                    ro = (ve * sn + vo * cs) * qscale;
                } else {
                    re = ve; ro = vo;
                }
                __half2* dp = (__half2*)(dsth + (((size_t)(b_ * NH + h)) * SEQ + s_) * DK + d);
                *dp = __floats2half2_rn(re, ro);
            }
        }
    }
}

// ============ WO GEMM ========================================================
__global__ __launch_bounds__(256) void gemm_out_kernel(float* __restrict__ out)
{
    const __half* __restrict__ A = g_Oh;
    const __half* __restrict__ W = g_Woh;

    GEMM_BODY(A, W)

    const int rb = m0 + wm * 64 + lr;
    const int cb = n0 + wn * 32 + 2 * lc;
    #pragma unroll
    for (int mf = 0; mf < 4; mf++) {
        #pragma unroll
        for (int nf = 0; nf < 4; nf++) {
            const int n = cb + nf * 8;
            #pragma unroll
            for (int half = 0; half < 2; half++) {
                const int m = rb + mf * 16 + half * 8;
                *(float2*)(out + (size_t)m * DM + n) =
                    make_float2(acc[mf][nf][half * 2], acc[mf][nf][half * 2 + 1]);
            }
        }
    }
}

// ====== fp16 flash attention: cp.async 3-stage K/V, ldmatrix (R12 exact) ====
#define FBM 64
#define FBN 64
#define FSTR 72
#define FQ_BYTES (64 * FSTR * 2)
#define FK_BYTES (64 * FSTR * 2)
#define FSTAGE_BYTES (2 * FK_BYTES)
#define FLASH_SMEM (FQ_BYTES + 3 * FSTAGE_BYTES)   // 64512

__global__ __launch_bounds__(128, 3) void flash_f16_kernel()
{
    extern __shared__ __half fsh[];
    const uint32_t fbase = (uint32_t)__cvta_generic_to_shared(fsh);
    const uint32_t qb = fbase;

    const int bh = blockIdx.y;
    const int m0 = ((int)gridDim.x - 1 - (int)blockIdx.x) * FBM;
    const int tid  = threadIdx.x;
    const int lane = tid & 31;
    const int w    = tid >> 5;
    const int lr   = lane >> 2;
    const int lc   = lane & 3;
    const int q8 = lane >> 3, r8 = lane & 7;

    const __half* __restrict__ Qb = g_Qh + (size_t)bh * SEQ * DK;
    const __half* __restrict__ Kb = g_Kh + (size_t)bh * SEQ * DK;
    const __half* __restrict__ Vb = g_Vh + (size_t)bh * SEQ * DK;

    const uint32_t qoff =
        ((w * 16 + (q8 & 1) * 8 + r8) * FSTR + (q8 >> 1) * 8) * 2;
    const uint32_t koff =
        ((((lane >> 4) & 1) * 8 + (lane & 7)) * FSTR + ((lane >> 3) & 1) * 8) * 2;
    const uint32_t voff =
        (((q8 & 1) * 8 + r8) * FSTR + (q8 >> 1) * 8) * 2;

    {
        #pragma unroll
        for (int it = 0; it < 4; it++) {
            const int idx = tid + it * 128;
            const int row = idx >> 3, ch = idx & 7;
            cp16(qb + (row * FSTR + ch * 8) * 2,
                 Qb + (size_t)(m0 + row) * DK + ch * 8);
        }
        CP_COMMIT();
    }

    auto issue_kv = [&](int t, int s) {
        const uint32_t kb = fbase + FQ_BYTES + s * FSTAGE_BYTES;
        const uint32_t vb = kb + FK_BYTES;
        const int j0 = t * FBN;
        #pragma unroll
        for (int it = 0; it < 4; it++) {
            const int idx = tid + it * 128;
            const int row = idx >> 3, ch = idx & 7;
            cp16(kb + (row * FSTR + ch * 8) * 2,
                 Kb + (size_t)(j0 + row) * DK + ch * 8);
            cp16(vb + (row * FSTR + ch * 8) * 2,
                 Vb + (size_t)(j0 + row) * DK + ch * 8);
        }
        CP_COMMIT();
    };

    const int nt = m0 / FBN + 1;
    issue_kv(0, 0);
    if (nt > 1) issue_kv(1, 1);

    uint32_t qf[4][4];
    {
        if (nt > 1) { CP_WAIT2(); } else { CP_WAIT1(); }
        __syncthreads();
        #pragma unroll
        for (int ks = 0; ks < 4; ks++)
            ldsm_x4(qf[ks][0], qf[ks][1], qf[ks][2], qf[ks][3],
                    qb + qoff + ks * 32);
    }

    float o[8][4];
    #pragma unroll
    for (int n = 0; n < 8; n++)
        #pragma unroll
        for (int c = 0; c < 4; c++) o[n][c] = 0.f;
    float mrow0 = -1e30f, mrow1 = -1e30f, lrow0 = 0.f, lrow1 = 0.f;

    for (int t = 0; t < nt; t++) {
        const int s = t % 3;
        if (t + 1 < nt) { CP_WAIT1(); } else { CP_WAIT0(); }
        __syncthreads();
        if (t + 2 < nt) issue_kv(t + 2, (t + 2) % 3);

        const uint32_t kb = fbase + FQ_BYTES + s * FSTAGE_BYTES;
        const uint32_t vb = kb + FK_BYTES;

        float sacc[8][4];
        #pragma unroll
        for (int n = 0; n < 8; n++)
            #pragma unroll
            for (int c = 0; c < 4; c++) sacc[n][c] = 0.f;

        #pragma unroll
        for (int ks = 0; ks < 4; ks++) {
            #pragma unroll
            for (int jp = 0; jp < 4; jp++) {
                uint32_t b0a, b1a, b0b, b1b;
                ldsm_x4(b0a, b1a, b0b, b1b,
                        kb + koff + (jp * 16 * FSTR + ks * 16) * 2);
                mma_f16(sacc[2*jp][0], sacc[2*jp][1], sacc[2*jp][2], sacc[2*jp][3],
                        qf[ks][0], qf[ks][1], qf[ks][2], qf[ks][3], b0a, b1a);
                mma_f16(sacc[2*jp+1][0], sacc[2*jp+1][1], sacc[2*jp+1][2], sacc[2*jp+1][3],
                        qf[ks][0], qf[ks][1], qf[ks][2], qf[ks][3], b0b, b1b);
            }
        }

        if (t == nt - 1) {
            const int r0 = w * 16 + lr;
            #pragma unroll
            for (int n = 0; n < 8; n++) {
                const int c0 = n * 8 + 2 * lc;
                if (c0     > r0)     sacc[n][0] = -1e30f;
                if (c0 + 1 > r0)     sacc[n][1] = -1e30f;
                if (c0     > r0 + 8) sacc[n][2] = -1e30f;
                if (c0 + 1 > r0 + 8) sacc[n][3] = -1e30f;
            }
        }

        float mx0 = -1e30f, mx1 = -1e30f;
        #pragma unroll
        for (int n = 0; n < 8; n++) {
            mx0 = fmaxf(mx0, fmaxf(sacc[n][0], sacc[n][1]));
            mx1 = fmaxf(mx1, fmaxf(sacc[n][2], sacc[n][3]));
        }
        mx0 = fmaxf(mx0, __shfl_xor_sync(0xffffffffu, mx0, 1));
        mx0 = fmaxf(mx0, __shfl_xor_sync(0xffffffffu, mx0, 2));
        mx1 = fmaxf(mx1, __shfl_xor_sync(0xffffffffu, mx1, 1));
        mx1 = fmaxf(mx1, __shfl_xor_sync(0xffffffffu, mx1, 2));

        const float mn0 = fmaxf(mrow0, mx0);
        const float mn1 = fmaxf(mrow1, mx1);
        const float sc0 = __expf(mrow0 - mn0);
        const float sc1 = __expf(mrow1 - mn1);
        lrow0 *= sc0; lrow1 *= sc1;
        #pragma unroll
        for (int n = 0; n < 8; n++) {
            o[n][0] *= sc0; o[n][1] *= sc0;
            o[n][2] *= sc1; o[n][3] *= sc1;
        }
        mrow0 = mn0; mrow1 = mn1;

        uint32_t pv[8][2];
        #pragma unroll
        for (int n = 0; n < 8; n++) {
            const float p0 = __expf(sacc[n][0] - mn0);
            const float p1 = __expf(sacc[n][1] - mn0);
            const float p2 = __expf(sacc[n][2] - mn1);
            const float p3 = __expf(sacc[n][3] - mn1);
            lrow0 += p0 + p1;
            lrow1 += p2 + p3;
            pv[n][0] = f2h2u(p0, p1);
            pv[n][1] = f2h2u(p2, p3);
        }

        #pragma unroll
        for (int ks = 0; ks < 4; ks++) {
            const uint32_t a0 = pv[2 * ks    ][0];
            const uint32_t a1 = pv[2 * ks    ][1];
            const uint32_t a2 = pv[2 * ks + 1][0];
            const uint32_t a3 = pv[2 * ks + 1][1];
            #pragma unroll
            for (int np = 0; np < 2; np++) {
                uint32_t b0a, b1a, b0b, b1b;
                ldsm_x4_t(b0a, b1a, b0b, b1b,
                          vb + voff + (ks * 16 * FSTR + np * 32) * 2);
                mma_f16(o[4*np  ][0], o[4*np  ][1], o[4*np  ][2], o[4*np  ][3],
                        a0, a1, a2, a3, b0a, b1a);
                mma_f16(o[4*np+1][0], o[4*np+1][1], o[4*np+1][2], o[4*np+1][3],
                        a0, a1, a2, a3, b0b, b1b);
                uint32_t c0a, c1a, c0b, c1b;
                ldsm_x4_t(c0a, c1a, c0b, c1b,
                          vb + voff + (ks * 16 * FSTR + np * 32 + 16) * 2);
                mma_f16(o[4*np+2][0], o[4*np+2][1], o[4*np+2][2], o[4*np+2][3],
                        a0, a1, a2, a3, c0a, c1a);
                mma_f16(o[4*np+3][0], o[4*np+3][1], o[4*np+3][2], o[4*np+3][3],
                        a0, a1, a2, a3, c0b, c1b);
            }
        }
        __syncthreads();
    }

    lrow0 += __shfl_xor_sync(0xffffffffu, lrow0, 1);
    lrow0 += __shfl_xor_sync(0xffffffffu, lrow0, 2);
    lrow1 += __shfl_xor_sync(0xffffffffu, lrow1, 1);
    lrow1 += __shfl_xor_sync(0xffffffffu, lrow1, 2);
    const float inv0 = 1.0f / lrow0;
    const float inv1 = 1.0f / lrow1;

    const int b_ = bh >> 4, h = bh & 15;
    const int r0 = m0 + w * 16 + lr;
    const int r1 = r0 + 8;
    #pragma unroll
    for (int n = 0; n < 8; n++) {
        const int d = h * 64 + n * 8 + 2 * lc;
        *(__half2*)(g_Oh + ((size_t)b_ * SEQ + r0) * DM + d) =
            __floats2half2_rn(o[n][0] * inv0, o[n][1] * inv0);
        *(__half2*)(g_Oh + ((size_t)b_ * SEQ + r1) * DM + d) =
            __floats2half2_rn(o[n][2] * inv1, o[n][3] * inv1);
    }
}

// ---------------- launch ----------------------------------------------------
extern "C" void kernel_launch(void* const* d_in, const int* in_sizes, int n_in,
                              void* d_out, int out_size)
{
    (void)in_sizes; (void)n_in; (void)out_size;
    const float* x   = (const float*)d_in[0];
    const int*   pos = (const int*)  d_in[1];
    const float* WQ  = (const float*)d_in[2];
    const float* WK  = (const float*)d_in[3];
    const float* WV  = (const float*)d_in[4];
    const float* WO  = (const float*)d_in[5];
    float* out = (float*)d_out;

    cudaFuncSetAttribute(gemm_qkv_kernel,
                         cudaFuncAttributeMaxDynamicSharedMemorySize, GEMM_SMEM);
    cudaFuncSetAttribute(gemm_out_kernel,
                         cudaFuncAttributeMaxDynamicSharedMemorySize, GEMM_SMEM);
    cudaFuncSetAttribute(flash_f16_kernel,
                         cudaFuncAttributeMaxDynamicSharedMemorySize, FLASH_SMEM);

    const int ncvt = (NX + 4 * NW) / (8 * 256);
    cvt_kernel<<<ncvt, 256>>>(x, WQ, WK, WV, WO);

    dim3 gq(DM / TBN, (BATCH * SEQ) / TBM, 3);      // (8, 32, 3)
    gemm_qkv_kernel<<<gq, 256, GEMM_SMEM>>>(pos);

    dim3 gf(SEQ / FBM, BATCH * NH);                 // (32, 32)
    flash_f16_kernel<<<gf, 128, FLASH_SMEM>>>();

    dim3 go(DM / TBN, (BATCH * SEQ) / TBM, 1);      // (8, 32)
    gemm_out_kernel<<<go, 256, GEMM_SMEM>>>(out);
}